// round 1
// baseline (speedup 1.0000x reference)
#include <cuda_runtime.h>
#include <cstdint>
#include <cstddef>

// Problem constants
#define T_TOKENS 65536   // 64*128*8
#define DDIM     256
#define PROTOS   512
#define BM       128     // tokens per block
#define BN       128     // proto chunk
#define NCHUNK   4       // PROTOS / BN
#define KSLICE   64
#define NSLICE   4       // DDIM / KSLICE
#define THREADS  256
#define NBLOCKS  (T_TOKENS / BM)   // 512

__device__ float g_pnorm[PROTOS];
__device__ float g_partials[NBLOCKS];

// ---------------------------------------------------------------------------
// Prototype squared norms
// ---------------------------------------------------------------------------
__global__ void pnorm_kernel(const float4* __restrict__ p4) {
    int n = blockIdx.x * blockDim.x + threadIdx.x;
    if (n < PROTOS) {
        float s = 0.f;
        #pragma unroll 8
        for (int kq = 0; kq < DDIM / 4; ++kq) {
            float4 v = p4[(size_t)n * (DDIM / 4) + kq];
            s += v.x * v.x + v.y * v.y + v.z * v.z + v.w * v.w;
        }
        g_pnorm[n] = s;
    }
}

// ---------------------------------------------------------------------------
// Main fused kernel: distance GEMM + argmin + gather + residual + loss partial
// ---------------------------------------------------------------------------
__global__ __launch_bounds__(THREADS, 1)
void vq_main_kernel(const float4* __restrict__ x4,
                    const float4* __restrict__ p4,
                    float4* __restrict__ out_proto,
                    float4* __restrict__ out_res) {
    extern __shared__ float sm[];
    float* sxT  = sm;                         // [DDIM][BM]  x transposed
    float* sp   = sm + DDIM * BM;             // [KSLICE][BN] proto slice
    int*   sidx = (int*)(sp + KSLICE * BN);   // [BM]
    float* sred = (float*)(sidx + BM);        // [THREADS]

    const int tid = threadIdx.x;
    const int tx  = tid & 15;    // proto dim (16)
    const int ty  = tid >> 4;    // token dim (16)
    const int t0  = blockIdx.x * BM;

    // Load x tile transposed: sxT[k][m]. Lanes have consecutive m -> STS conflict-free.
    for (int i = tid; i < BM * (DDIM / 4); i += THREADS) {
        int t  = i & (BM - 1);
        int kq = i >> 7;
        float4 v = x4[(size_t)(t0 + t) * (DDIM / 4) + kq];
        sxT[(4 * kq + 0) * BM + t] = v.x;
        sxT[(4 * kq + 1) * BM + t] = v.y;
        sxT[(4 * kq + 2) * BM + t] = v.z;
        sxT[(4 * kq + 3) * BM + t] = v.w;
    }

    float best[8];
    int   bidx[8];
    #pragma unroll
    for (int i = 0; i < 8; i++) { best[i] = 3.4e38f; bidx[i] = 0; }

    for (int c = 0; c < NCHUNK; ++c) {
        float acc[8][8];
        #pragma unroll
        for (int i = 0; i < 8; i++)
            #pragma unroll
            for (int j = 0; j < 8; j++) acc[i][j] = 0.f;

        for (int s = 0; s < NSLICE; ++s) {
            __syncthreads();   // prior compute done before sp overwrite (also fences x load, 1st iter)
            // Load proto K-slice: sp[kl][n]
            for (int i = tid; i < BN * (KSLICE / 4); i += THREADS) {
                int n  = i & (BN - 1);
                int kq = i >> 7;   // 0..15
                float4 v = p4[(size_t)(c * BN + n) * (DDIM / 4) + s * (KSLICE / 4) + kq];
                sp[(4 * kq + 0) * BN + n] = v.x;
                sp[(4 * kq + 1) * BN + n] = v.y;
                sp[(4 * kq + 2) * BN + n] = v.z;
                sp[(4 * kq + 3) * BN + n] = v.w;
            }
            __syncthreads();

            const float* xrow = sxT + (s * KSLICE) * BM + ty * 8;
            const float* prow = sp + tx * 8;
            #pragma unroll 8
            for (int k = 0; k < KSLICE; ++k) {
                float4 a0 = *(const float4*)(xrow + k * BM);
                float4 a1 = *(const float4*)(xrow + k * BM + 4);
                float4 b0 = *(const float4*)(prow + k * BN);
                float4 b1 = *(const float4*)(prow + k * BN + 4);
                float a[8] = {a0.x, a0.y, a0.z, a0.w, a1.x, a1.y, a1.z, a1.w};
                float b[8] = {b0.x, b0.y, b0.z, b0.w, b1.x, b1.y, b1.z, b1.w};
                #pragma unroll
                for (int mi = 0; mi < 8; ++mi)
                    #pragma unroll
                    for (int nj = 0; nj < 8; ++nj)
                        acc[mi][nj] = fmaf(a[mi], b[nj], acc[mi][nj]);
            }
        }

        // Merge this chunk into running argmin. dist = ||p||^2 - 2*dot (token norm constant).
        #pragma unroll
        for (int nj = 0; nj < 8; ++nj) {
            int   ng = c * BN + tx * 8 + nj;
            float pn = g_pnorm[ng];
            #pragma unroll
            for (int mi = 0; mi < 8; ++mi) {
                float dst = fmaf(-2.f, acc[mi][nj], pn);
                if (dst < best[mi]) { best[mi] = dst; bidx[mi] = ng; }
            }
        }
    }

    // Reduce argmin across the 16 proto-dim lanes (lanes 0-15 / 16-31 within warp).
    #pragma unroll
    for (int off = 8; off >= 1; off >>= 1) {
        #pragma unroll
        for (int mi = 0; mi < 8; ++mi) {
            float od = __shfl_xor_sync(0xffffffffu, best[mi], off);
            int   oi = __shfl_xor_sync(0xffffffffu, bidx[mi], off);
            if (od < best[mi] || (od == best[mi] && oi < bidx[mi])) {
                best[mi] = od; bidx[mi] = oi;
            }
        }
    }
    if (tx == 0) {
        #pragma unroll
        for (int mi = 0; mi < 8; ++mi) sidx[ty * 8 + mi] = bidx[mi];
    }
    __syncthreads();

    // Epilogue: gather prototype, write proto + residual (coalesced), loss partial.
    float lsum = 0.f;
    for (int i = tid; i < BM * (DDIM / 4); i += THREADS) {
        int t  = i >> 6;        // lanes share t, walk kq -> coalesced
        int kq = i & 63;
        int id = sidx[t];
        float4 pv = p4[(size_t)id * (DDIM / 4) + kq];
        float4 xv = x4[(size_t)(t0 + t) * (DDIM / 4) + kq];
        float4 rv = make_float4(xv.x - pv.x, xv.y - pv.y, xv.z - pv.z, xv.w - pv.w);
        size_t o = (size_t)(t0 + t) * (DDIM / 4) + kq;
        out_proto[o] = pv;
        out_res[o]   = rv;
        lsum += rv.x * rv.x + rv.y * rv.y + rv.z * rv.z + rv.w * rv.w;
    }

    // Deterministic block reduction of loss partial.
    sred[tid] = lsum;
    __syncthreads();
    #pragma unroll
    for (int s2 = THREADS / 2; s2 >= 1; s2 >>= 1) {
        if (tid < s2) sred[tid] += sred[tid + s2];
        __syncthreads();
    }
    if (tid == 0) g_partials[blockIdx.x] = sred[0];
}

// ---------------------------------------------------------------------------
// Deterministic final loss reduction
// ---------------------------------------------------------------------------
__global__ void finalize_kernel(float* __restrict__ loss_out) {
    __shared__ float s[NBLOCKS];
    int tid = threadIdx.x;
    s[tid] = g_partials[tid];
    __syncthreads();
    #pragma unroll
    for (int st = NBLOCKS / 2; st >= 1; st >>= 1) {
        if (tid < st) s[tid] += s[tid + st];
        __syncthreads();
    }
    if (tid == 0) {
        // loss = q_latent + 0.25 * e_latent = 1.25 * mean((proto - x)^2)
        *loss_out = 1.25f * s[0] / 16777216.0f;
    }
}

// ---------------------------------------------------------------------------
extern "C" void kernel_launch(void* const* d_in, const int* in_sizes, int n_in,
                              void* d_out, int out_size) {
    const float4* x4 = (const float4*)d_in[0];
    const float4* p4 = (const float4*)d_in[1];
    float* out = (float*)d_out;

    float4* out_proto = (float4*)out;                          // [65536, 256]
    float4* out_res   = (float4*)(out + 16777216);             // [65536, 256]
    float*  loss_out  = out + 33554432;                        // scalar

    const int smem_bytes = (DDIM * BM + KSLICE * BN) * 4 + BM * 4 + THREADS * 4;
    cudaFuncSetAttribute(vq_main_kernel,
                         cudaFuncAttributeMaxDynamicSharedMemorySize, smem_bytes);

    pnorm_kernel<<<2, 256>>>(p4);
    vq_main_kernel<<<NBLOCKS, THREADS, smem_bytes>>>(x4, p4, out_proto, out_res);
    finalize_kernel<<<1, NBLOCKS>>>(loss_out);
}